// round 7
// baseline (speedup 1.0000x reference)
#include <cuda_runtime.h>
#include <cuda_bf16.h>
#include <cstdint>
#include <cstddef>

#define B_   16
#define S_   2048
#define D_   256
#define GD_  1024
#define L_   4
#define NTOK (B_*S_)
#define CL   8

// ---- scratch (device globals: no allocations allowed) ----
__device__ float g_h [(size_t)NTOK*D_];     // residual stream [B,S,D]   (32 MB)
__device__ float g_gx[(size_t)NTOK*GD_];    // gate preacts    [B,S,4D]  (128 MB)
__device__ float g_mu[NTOK];
__device__ float g_rs[NTOK];

typedef unsigned long long ull;

__device__ __forceinline__ ull pack2(float x, float y){
    ull r; asm("mov.b64 %0,{%1,%2};" : "=l"(r) : "f"(x), "f"(y)); return r;
}
__device__ __forceinline__ float2 unpack2(ull v){
    float2 f; asm("mov.b64 {%0,%1},%2;" : "=f"(f.x), "=f"(f.y) : "l"(v)); return f;
}
__device__ __forceinline__ void fma2(ull& d, ull a, ull b){
    asm("fma.rn.f32x2 %0,%1,%2,%0;" : "+l"(d) : "l"(a), "l"(b));
}

// ============================================================
// 1) input projection: h = concat(x, time_feats) @ in_W + in_b
// ============================================================
__global__ void k_inproj(const float* __restrict__ x, const float* __restrict__ tf,
                         const float* __restrict__ W, const float* __restrict__ b)
{
    int t = blockIdx.x;          // token 0..32767
    int d = threadIdx.x;         // 0..255
    float acc = b[d] + x[t]*W[d];
    const float* tft = tf + (size_t)t*6;
    #pragma unroll
    for(int f=0; f<6; f++) acc = fmaf(tft[f], W[(f+1)*D_ + d], acc);
    g_h[(size_t)t*D_ + d] = acc;
}

// ============================================================
// 2) per-token layernorm stats (mean, rstd): 1 warp per token
// ============================================================
__global__ void k_lnstats()
{
    int warp = threadIdx.x >> 5, lane = threadIdx.x & 31;
    int t = blockIdx.x*8 + warp;
    const float4* p = (const float4*)(g_h + (size_t)t*D_) + lane*2;
    float4 v0 = p[0], v1 = p[1];
    float s = v0.x+v0.y+v0.z+v0.w + v1.x+v1.y+v1.z+v1.w;
    float q = v0.x*v0.x+v0.y*v0.y+v0.z*v0.z+v0.w*v0.w
            + v1.x*v1.x+v1.y*v1.y+v1.z*v1.z+v1.w*v1.w;
    #pragma unroll
    for(int o=16;o;o>>=1){ s += __shfl_xor_sync(~0u,s,o); q += __shfl_xor_sync(~0u,q,o); }
    if(lane==0){
        float mu  = s * (1.f/256.f);
        float var = q * (1.f/256.f) - mu*mu;
        g_mu[t] = mu;
        g_rs[t] = rsqrtf(var + 1e-5f);
    }
}

// ============================================================
// 3) gx = (LN(h)*g+b) @ Wx + bg   (128x128 tile, K-chunk 8, f32x2 accs)
//    grid (8, 256), 256 threads
// ============================================================
__global__ __launch_bounds__(256)
void k_gemm(const float* __restrict__ Wx, const float* __restrict__ bg,
            const float* __restrict__ lng, const float* __restrict__ lnb)
{
    __shared__ __align__(16) float As[8*128];
    __shared__ __align__(16) float Bs[8*128];

    int tid = threadIdx.x;
    int m0 = blockIdx.y*128, n0 = blockIdx.x*128;
    int tx = tid & 15, ty = tid >> 4;

    ull acc[8][4];
    #pragma unroll
    for(int i=0;i<8;i++)
        #pragma unroll
        for(int j=0;j<4;j++) acc[i][j]=0ULL;

    int arow = tid>>1, akp = (tid&1)*4;
    float amu = g_mu[m0+arow], ars = g_rs[m0+arow];
    int bkk = tid>>5, bn = (tid&31)*4;

    for(int kb=0; kb<D_; kb+=8){
        float4 av = *(const float4*)(g_h + (size_t)(m0+arow)*D_ + kb + akp);
        float4 lg = *(const float4*)(lng + kb + akp);
        float4 lb = *(const float4*)(lnb + kb + akp);
        As[(akp+0)*128+arow] = (av.x-amu)*ars*lg.x + lb.x;
        As[(akp+1)*128+arow] = (av.y-amu)*ars*lg.y + lb.y;
        As[(akp+2)*128+arow] = (av.z-amu)*ars*lg.z + lb.z;
        As[(akp+3)*128+arow] = (av.w-amu)*ars*lg.w + lb.w;
        *(float4*)(Bs + bkk*128 + bn) =
            *(const float4*)(Wx + (size_t)(kb+bkk)*GD_ + n0 + bn);
        __syncthreads();
        #pragma unroll
        for(int kk=0; kk<8; kk++){
            float4 a0 = *(const float4*)(As + kk*128 + ty*8);
            float4 a1 = *(const float4*)(As + kk*128 + ty*8 + 4);
            const ull* b2 = (const ull*)(Bs + kk*128 + tx*8);
            ull bb0=b2[0], bb1=b2[1], bb2=b2[2], bb3=b2[3];
            float a[8] = {a0.x,a0.y,a0.z,a0.w,a1.x,a1.y,a1.z,a1.w};
            #pragma unroll
            for(int i=0;i<8;i++){
                ull a2 = pack2(a[i], a[i]);
                fma2(acc[i][0], a2, bb0);
                fma2(acc[i][1], a2, bb1);
                fma2(acc[i][2], a2, bb2);
                fma2(acc[i][3], a2, bb3);
            }
        }
        __syncthreads();
    }
    float4 bg0 = *(const float4*)(bg + n0 + tx*8);
    float4 bg1 = *(const float4*)(bg + n0 + tx*8 + 4);
    #pragma unroll
    for(int i=0;i<8;i++){
        float* C = g_gx + (size_t)(m0+ty*8+i)*GD_ + n0 + tx*8;
        float2 c0=unpack2(acc[i][0]), c1=unpack2(acc[i][1]);
        float2 c2=unpack2(acc[i][2]), c3=unpack2(acc[i][3]);
        float4 o0 = make_float4(c0.x+bg0.x, c0.y+bg0.y, c1.x+bg0.z, c1.y+bg0.w);
        float4 o1 = make_float4(c2.x+bg1.x, c2.y+bg1.y, c3.x+bg1.z, c3.y+bg1.w);
        *(float4*)C       = o0;
        *(float4*)(C + 4) = o1;
    }
}

// ============================================================
// 4) sLSTM recurrence: 1 batch per 8-CTA cluster, Wh in registers
//    grid 128 CTAs x 512 threads, cluster (8,1,1)
//    CTA rank r owns hidden dims [r*32, r*32+32) -> gate cols
//    {g*256 + r*32 + dl : g in 0..3, dl in 0..31} (128 local cols)
// ============================================================
__global__ void __launch_bounds__(512,1) __cluster_dims__(CL,1,1)
k_slstm(const float* __restrict__ Wh)
{
    __shared__ __align__(16) float h_buf[2][256];    // hs double-buffered (DSMEM target)
    __shared__ __align__(16) float staging[16*128];  // [warp][localcol] partials
    __shared__ __align__(16) float g_arr[128];       // reduced gates [gate*32+dl]
    __shared__ __align__(16) float gxbuf[2][128];    // prefetched gx slice
    __shared__ __align__(16) float hold_buf[2][32];  // prefetched residual slice

    int tid  = threadIdx.x;
    int lane = tid & 31, warp = tid >> 5;
    uint32_t rank;
    asm("mov.u32 %0, %%cluster_ctarank;" : "=r"(rank));
    int batch = blockIdx.x >> 3;

    // ---- register-resident Wh slice:
    //      warp owns k in [warp*16, warp*16+16); lane owns 4 local cols.
    //      local col lc -> global col (lc>>5)*256 + rank*32 + (lc&31)
    ull w2[4][8];
    int k0 = warp*16;
    #pragma unroll
    for(int c=0;c<4;c++){
        int lc = lane*4 + c;
        int colg = (lc>>5)*256 + (int)rank*32 + (lc&31);
        #pragma unroll
        for(int j=0;j<8;j++){
            int k = k0 + 2*j;
            w2[c][j] = pack2(Wh[(size_t)k*GD_ + colg], Wh[(size_t)(k+1)*GD_ + colg]);
        }
    }

    if(tid < 256) h_buf[0][tid] = 0.f;
    float c_st=0.f, n_st=0.f, m_st=0.f;

    const float* gx_b = g_gx + (size_t)batch*S_*GD_;
    float*       h_bp = g_h  + (size_t)batch*S_*D_;   // read (residual in) + write (out)

    // ---- prefetch t=0 (warp 14)
    if(warp == 14){
        int gate = lane>>3, d0p = (lane&7)*4;
        uint32_t dstgx = (uint32_t)__cvta_generic_to_shared(&gxbuf[0][gate*32 + d0p]);
        const float* src = gx_b + gate*256 + (int)rank*32 + d0p;
        asm volatile("cp.async.cg.shared.global [%0], [%1], 16;" :: "r"(dstgx), "l"(src));
        if(lane < 8){
            uint32_t dsth = (uint32_t)__cvta_generic_to_shared(&hold_buf[0][lane*4]);
            const float* srch = h_bp + (int)rank*32 + lane*4;
            asm volatile("cp.async.cg.shared.global [%0], [%1], 16;" :: "r"(dsth), "l"(srch));
        }
        asm volatile("cp.async.commit_group;");
    }
    __syncthreads();

    for(int t=0; t<S_; t++){
        int cur = t & 1, nxt = cur ^ 1;

        // warp 14: complete this step's prefetch, issue next step's
        if(warp == 14){
            asm volatile("cp.async.wait_group 0;" ::: "memory");
            if(t+1 < S_){
                int gate = lane>>3, d0p = (lane&7)*4;
                uint32_t dstgx = (uint32_t)__cvta_generic_to_shared(&gxbuf[nxt][gate*32 + d0p]);
                const float* src = gx_b + (size_t)(t+1)*GD_ + gate*256 + (int)rank*32 + d0p;
                asm volatile("cp.async.cg.shared.global [%0], [%1], 16;" :: "r"(dstgx), "l"(src));
                if(lane < 8){
                    uint32_t dsth = (uint32_t)__cvta_generic_to_shared(&hold_buf[nxt][lane*4]);
                    const float* srch = h_bp + (size_t)(t+1)*D_ + (int)rank*32 + lane*4;
                    asm volatile("cp.async.cg.shared.global [%0], [%1], 16;" :: "r"(dsth), "l"(srch));
                }
                asm volatile("cp.async.commit_group;");
            }
        }

        // ---- partial dots: hs[k0..k0+16) . Wh[k, my 4 local cols]
        const ull* hb2 = (const ull*)h_buf[cur] + (k0>>1);
        ull a0=0ULL, a1=0ULL, a2v=0ULL, a3=0ULL;
        #pragma unroll
        for(int j=0;j<8;j++){
            ull h2 = hb2[j];                 // broadcast LDS.64
            fma2(a0,  h2, w2[0][j]);
            fma2(a1,  h2, w2[1][j]);
            fma2(a2v, h2, w2[2][j]);
            fma2(a3,  h2, w2[3][j]);
        }
        float2 p0=unpack2(a0), p1=unpack2(a1), p2=unpack2(a2v), p3=unpack2(a3);
        *(float4*)(staging + warp*128 + lane*4) =
            make_float4(p0.x+p0.y, p1.x+p1.y, p2.x+p2.y, p3.x+p3.y);
        __syncthreads();

        // ---- reduce 16 warp partials per local col + add gx (warps 0-3)
        if(warp < 4){
            int lc = tid;                    // 0..127
            float s = 0.f;
            #pragma unroll
            for(int w=0; w<16; w++) s += staging[w*128 + lc];
            g_arr[lc] = s + gxbuf[cur][lc];
        }
        if(warp < 4 || warp == 15)
            asm volatile("bar.sync 1, 160;" ::: "memory");

        // ---- gating (warp 15, lane = local dim)
        if(warp == 15){
            float i_t = g_arr[lane],      f_t = g_arr[32+lane];
            float z_t = g_arr[64+lane],   o_t = g_arr[96+lane];
            float m_new = fmaxf(f_t + m_st, i_t);
            float ip = __expf(i_t - m_new);
            float fp = __expf(f_t + m_st - m_new);
            m_st = m_new;
            c_st = fp*c_st + ip*tanhf(z_t);
            n_st = fp*n_st + ip;
            float sig = 1.f/(1.f + __expf(-o_t));
            float hval = sig * c_st / fmaxf(fabsf(n_st), 1.f);

            // push new hs to all 8 CTAs' h_buf[nxt][rank*32+lane]
            uint32_t laddr = (uint32_t)__cvta_generic_to_shared(
                                 &h_buf[nxt][(int)rank*32 + lane]);
            #pragma unroll
            for(int r=0;r<CL;r++){
                uint32_t raddr;
                asm volatile("mapa.shared::cluster.u32 %0, %1, %2;"
                             : "=r"(raddr) : "r"(laddr), "r"(r));
                asm volatile("st.shared::cluster.f32 [%0], %1;"
                             :: "r"(raddr), "f"(hval) : "memory");
            }
            // residual stream out: h = h + hs
            h_bp[(size_t)t*D_ + (int)rank*32 + lane] = hold_buf[cur][lane] + hval;
        }

        // ---- cluster barrier: publishes DSMEM h pushes (arrive=release)
        asm volatile("barrier.cluster.arrive.aligned;" ::: "memory");
        asm volatile("barrier.cluster.wait.aligned;"   ::: "memory");
    }
}

// ============================================================
// 5) head: out[b] = h[b, S-1, :] @ fc_W + fc_b
// ============================================================
__global__ void k_head(const float* __restrict__ fcW, const float* __restrict__ fcb,
                       float* __restrict__ out)
{
    __shared__ float red[8];
    int b = blockIdx.x, tid = threadIdx.x;
    int lane = tid & 31, warp = tid >> 5;
    float v = g_h[((size_t)b*S_ + (S_-1))*D_ + tid] * fcW[tid];
    #pragma unroll
    for(int o=16;o;o>>=1) v += __shfl_xor_sync(~0u, v, o);
    if(lane==0) red[warp] = v;
    __syncthreads();
    if(tid==0){
        float s = 0.f;
        #pragma unroll
        for(int w=0;w<8;w++) s += red[w];
        out[b] = s + fcb[0];
    }
}

// ============================================================
extern "C" void kernel_launch(void* const* d_in, const int* in_sizes, int n_in,
                              void* d_out, int out_size)
{
    (void)in_sizes; (void)n_in; (void)out_size;
    const float* x    = (const float*)d_in[0];
    const float* tf   = (const float*)d_in[1];
    const float* in_W = (const float*)d_in[2];
    const float* in_b = (const float*)d_in[3];
    const float* ln_g = (const float*)d_in[4];
    const float* ln_b = (const float*)d_in[5];
    const float* Wx   = (const float*)d_in[6];
    const float* Wh   = (const float*)d_in[7];
    const float* bg   = (const float*)d_in[8];
    const float* fc_W = (const float*)d_in[9];
    const float* fc_b = (const float*)d_in[10];
    float* out = (float*)d_out;

    k_inproj<<<NTOK, 256>>>(x, tf, in_W, in_b);
    for(int l=0; l<L_; l++){
        k_lnstats<<<NTOK/8, 256>>>();
        k_gemm<<<dim3(8,256), 256>>>(Wx + (size_t)l*D_*GD_, bg + (size_t)l*GD_,
                                     ln_g + (size_t)l*D_, ln_b + (size_t)l*D_);
        k_slstm<<<B_*CL, 512>>>(Wh + (size_t)l*D_*GD_);
    }
    k_head<<<B_, 256>>>(fc_W, fc_b, out);
}